// round 1
// baseline (speedup 1.0000x reference)
#include <cuda_runtime.h>
#include <math.h>

#define B_      2
#define T_      4096
#define DIM_    1024
#define HEADS_  8
#define DH_     128
#define NHASH_  4
#define NB_     64
#define BUCKET_ 64
#define BH_     16
#define BT_     8192
#define FF_     4096
#define NCH_    256          // chunks per bh = NHASH_*NB_
#define NSORT_  16384        // NHASH_*T_
#define SCALE_  0.08838834764831845f
#define SELF_VAL_ (-5e4f)

// ---------------- scratch (device globals; no allocation allowed) ----------
__device__ float g_x1[BT_*DIM_];
__device__ float g_x2[BT_*DIM_];
__device__ float g_xn[BT_*DIM_];
__device__ float g_qk[BT_*DIM_];
__device__ float g_v [BT_*DIM_];
__device__ float g_attn[BT_*DIM_];
__device__ float g_ff[BT_*FF_];
__device__ float g_orounds[BH_*NHASH_*T_*DH_];
__device__ float g_lse[BH_*NHASH_*T_];
__device__ int   g_keys[BH_*NSORT_];

// ---------------- layernorm ----------------
__global__ void ln_kernel(const float* __restrict__ x, const float* __restrict__ g,
                          const float* __restrict__ bta, float* __restrict__ y) {
    int row = blockIdx.x;
    int tid = threadIdx.x;                    // 256
    const float* xr = x + (size_t)row * DIM_;
    float s = 0.f, sq = 0.f;
    for (int d = tid; d < DIM_; d += 256) {
        float v = xr[d];
        s += v; sq += v * v;
    }
    // block reduce
    __shared__ float rs[8], rq[8];
    for (int o = 16; o > 0; o >>= 1) {
        s  += __shfl_down_sync(0xffffffff, s,  o);
        sq += __shfl_down_sync(0xffffffff, sq, o);
    }
    int warp = tid >> 5, lane = tid & 31;
    if (lane == 0) { rs[warp] = s; rq[warp] = sq; }
    __syncthreads();
    if (warp == 0) {
        s  = (lane < 8) ? rs[lane] : 0.f;
        sq = (lane < 8) ? rq[lane] : 0.f;
        for (int o = 4; o > 0; o >>= 1) {
            s  += __shfl_down_sync(0xffffffff, s,  o);
            sq += __shfl_down_sync(0xffffffff, sq, o);
        }
        if (lane == 0) { rs[0] = s; rq[0] = sq; }
    }
    __syncthreads();
    float mean = rs[0] * (1.0f / DIM_);
    float var  = rq[0] * (1.0f / DIM_) - mean * mean;
    float rstd = rsqrtf(var + 1e-5f);
    float* yr = y + (size_t)row * DIM_;
    for (int d = tid; d < DIM_; d += 256)
        yr[d] = (xr[d] - mean) * rstd * g[d] + bta[d];
}

// ---------------- generic fp32 GEMM: C = A[M,K] @ B[K,N] (+bias)(gelu)(+resid)
__global__ void gemm_kernel(const float* __restrict__ A, const float* __restrict__ Bm,
                            const float* __restrict__ bias, const float* __restrict__ resid,
                            float* __restrict__ C, int M, int N, int K, int act) {
    __shared__ float As[16][65];   // [k][m]
    __shared__ float Bs[16][64];   // [k][n]
    int bm = blockIdx.y, bn = blockIdx.x;
    int tid = threadIdx.x;         // 256
    int ty = tid >> 4, tx = tid & 15;
    float acc[4][4];
#pragma unroll
    for (int i = 0; i < 4; i++)
#pragma unroll
        for (int j = 0; j < 4; j++) acc[i][j] = 0.f;

    int aRow = bm * 64 + (tid >> 2);
    int aCol = (tid & 3) * 4;
    int bRow = tid >> 4;
    int bCol = (tid & 15) * 4;

    for (int kt = 0; kt < K; kt += 16) {
        float4 a4 = *(const float4*)&A[(size_t)aRow * K + kt + aCol];
        As[aCol + 0][tid >> 2] = a4.x;
        As[aCol + 1][tid >> 2] = a4.y;
        As[aCol + 2][tid >> 2] = a4.z;
        As[aCol + 3][tid >> 2] = a4.w;
        float4 b4 = *(const float4*)&Bm[(size_t)(kt + bRow) * N + bn * 64 + bCol];
        *(float4*)&Bs[bRow][bCol] = b4;
        __syncthreads();
#pragma unroll
        for (int k = 0; k < 16; k++) {
            float a[4], b[4];
#pragma unroll
            for (int i = 0; i < 4; i++) a[i] = As[k][ty * 4 + i];
#pragma unroll
            for (int j = 0; j < 4; j++) b[j] = Bs[k][tx * 4 + j];
#pragma unroll
            for (int i = 0; i < 4; i++)
#pragma unroll
                for (int j = 0; j < 4; j++) acc[i][j] += a[i] * b[j];
        }
        __syncthreads();
    }
#pragma unroll
    for (int i = 0; i < 4; i++) {
        int r = bm * 64 + ty * 4 + i;
#pragma unroll
        for (int j = 0; j < 4; j++) {
            int c = bn * 64 + tx * 4 + j;
            float v = acc[i][j];
            if (bias) v += bias[c];
            if (act)  v = 0.5f * v * (1.0f + erff(v * 0.70710678118654752f));
            if (resid) v += resid[(size_t)r * N + c];
            C[(size_t)r * N + c] = v;
        }
    }
}

// ---------------- LSH hashing: buckets + sort keys -------------------------
// grid: BH_*64 blocks (64-token tiles), 256 threads, dyn smem 98304
__global__ void hash_kernel(const float* __restrict__ qk, const float* __restrict__ rot,
                            int* __restrict__ keys) {
    extern __shared__ float sm[];
    float* rotS = sm;              // [128*4*32] = 16384
    float* qS   = sm + 16384;      // [64][128]  = 8192
    int bh = blockIdx.x >> 6;
    int tile = blockIdx.x & 63;
    int b = bh >> 3, h = bh & 7;
    int tid = threadIdx.x;
    for (int idx = tid; idx < 16384; idx += 256) rotS[idx] = rot[idx];
    int t0 = tile * 64;
    for (int idx = tid; idx < 8192; idx += 256) {
        int tok = idx >> 7, d = idx & 127;
        qS[idx] = qk[((size_t)(b * T_ + t0 + tok)) * DIM_ + h * DH_ + d];
    }
    __syncthreads();
    int tg = tid >> 7;             // token group 0/1
    int combo = tid & 127;
    int hh = combo >> 5, i = combo & 31;
    for (int pass = 0; pass < 4; pass++) {
        int base = (pass * 2 + tg) * 8;
        float acc[8];
#pragma unroll
        for (int u = 0; u < 8; u++) acc[u] = 0.f;
        for (int d = 0; d < 128; d++) {
            float rv = rotS[(d * 4 + hh) * 32 + i];
#pragma unroll
            for (int u = 0; u < 8; u++) acc[u] += qS[(base + u) * 128 + d] * rv;
        }
#pragma unroll
        for (int u = 0; u < 8; u++) {
            float v; int idx;
            if (acc[u] >= -acc[u]) { v = acc[u];  idx = i; }
            else                   { v = -acc[u]; idx = i + 32; }
            for (int o = 16; o > 0; o >>= 1) {
                float ov = __shfl_down_sync(0xffffffff, v, o);
                int   oi = __shfl_down_sync(0xffffffff, idx, o);
                if (ov > v || (ov == v && oi < idx)) { v = ov; idx = oi; }
            }
            if (i == 0) {
                int t = t0 + base + u;
                int bucket = idx + hh * NB_;
                keys[bh * NSORT_ + hh * T_ + t] = bucket * T_ + t;
            }
        }
    }
}

// ---------------- bitonic sort of 16384 unique keys per bh -----------------
__global__ void sort_kernel(int* __restrict__ keys) {
    extern __shared__ int sk[];            // 16384 ints
    int bh = blockIdx.x;
    int tid = threadIdx.x;                 // 1024
    for (int i = tid; i < NSORT_; i += 1024) sk[i] = keys[bh * NSORT_ + i];
    __syncthreads();
    for (int k = 2; k <= NSORT_; k <<= 1) {
        for (int j = k >> 1; j > 0; j >>= 1) {
            for (int i = tid; i < NSORT_; i += 1024) {
                int ixj = i ^ j;
                if (ixj > i) {
                    int a = sk[i], c = sk[ixj];
                    bool up = ((i & k) == 0);
                    if ((a > c) == up) { sk[i] = c; sk[ixj] = a; }
                }
            }
            __syncthreads();
        }
    }
    for (int i = tid; i < NSORT_; i += 1024) keys[bh * NSORT_ + i] = sk[i];
}

// ---------------- chunked attention ----------------------------------------
// grid: BH_*NCH_ blocks, 256 threads, dyn smem 135424
__global__ void attn_kernel(const float* __restrict__ qk, const float* __restrict__ vg,
                            const int* __restrict__ keys, float* __restrict__ orounds,
                            float* __restrict__ lseg) {
    extern __shared__ float sm[];
    float* qS   = sm;                       // 64*132
    float* kvS  = qS + 64 * 132;            // 128*132
    float* dots = kvS + 128 * 132;          // 64*128
    float* lseS = dots + 64 * 128;          // 64
    int*   tq   = (int*)(lseS + 64);        // 64
    int*   hq   = tq + 64;                  // 64
    int*   tk   = hq + 64;                  // 128

    int blk = blockIdx.x;
    int bh = blk >> 8;                      // NCH_=256
    int c  = blk & 255;
    int cp = (c + NCH_ - 1) & 255;
    int b = bh >> 3, h = bh & 7;
    int tid = threadIdx.x;

    if (tid < 128) {
        int j = tid;
        int ch = (j < 64) ? c : cp;
        int p = ch * 64 + (j & 63);
        int key = keys[bh * NSORT_ + p];
        int t = key & (T_ - 1);
        tk[j] = t;
        if (j < 64) { tq[j] = t; hq[j] = key >> 18; }
    }
    __syncthreads();

    // load q rows (raw) and k rows (to be normalized)
    for (int idx = tid; idx < 64 * 128; idx += 256) {
        int i = idx >> 7, d = idx & 127;
        qS[i * 132 + d] = qk[((size_t)(b * T_ + tq[i])) * DIM_ + h * DH_ + d];
    }
    for (int idx = tid; idx < 128 * 128; idx += 256) {
        int j = idx >> 7, d = idx & 127;
        kvS[j * 132 + d] = qk[((size_t)(b * T_ + tk[j])) * DIM_ + h * DH_ + d];
    }
    __syncthreads();

    // normalize k rows
    if (tid < 128) {
        float ss = 0.f;
        for (int d = 0; d < 128; d++) { float v = kvS[tid * 132 + d]; ss += v * v; }
        float inv = 1.0f / fmaxf(sqrtf(ss), 1e-12f);
        for (int d = 0; d < 128; d++) kvS[tid * 132 + d] *= inv;
    }
    __syncthreads();

    // dots: 4 rows x 8 cols micro-tile per thread
    {
        int it = tid >> 4, jt = tid & 15;
        int i0 = it * 4;
        float acc[4][8];
#pragma unroll
        for (int u = 0; u < 4; u++)
#pragma unroll
            for (int w = 0; w < 8; w++) acc[u][w] = 0.f;
        for (int d = 0; d < 128; d++) {
            float a[4], bb[8];
#pragma unroll
            for (int u = 0; u < 4; u++) a[u] = qS[(i0 + u) * 132 + d];
#pragma unroll
            for (int w = 0; w < 8; w++) bb[w] = kvS[(jt + w * 16) * 132 + d];
#pragma unroll
            for (int u = 0; u < 4; u++)
#pragma unroll
                for (int w = 0; w < 8; w++) acc[u][w] += a[u] * bb[w];
        }
#pragma unroll
        for (int u = 0; u < 4; u++) {
            int ti = tq[i0 + u];
#pragma unroll
            for (int w = 0; w < 8; w++) {
                int j = jt + w * 16;
                float v = (ti == tk[j]) ? SELF_VAL_ : acc[u][w] * SCALE_;
                dots[(i0 + u) * 128 + j] = v;
            }
        }
    }
    __syncthreads();

    // softmax per row, store p in dots, lse in lseS
    {
        int warp = tid >> 5, lane = tid & 31;
        for (int rr = 0; rr < 8; rr++) {
            int i = warp * 8 + rr;
            float m = -3.0e38f;
#pragma unroll
            for (int u = 0; u < 4; u++) m = fmaxf(m, dots[i * 128 + lane + u * 32]);
            for (int o = 16; o > 0; o >>= 1) m = fmaxf(m, __shfl_xor_sync(0xffffffff, m, o));
            float s = 0.f;
#pragma unroll
            for (int u = 0; u < 4; u++) s += expf(dots[i * 128 + lane + u * 32] - m);
            for (int o = 16; o > 0; o >>= 1) s += __shfl_xor_sync(0xffffffff, s, o);
            float lse = m + logf(s);
#pragma unroll
            for (int u = 0; u < 4; u++) {
                int col = lane + u * 32;
                dots[i * 128 + col] = expf(dots[i * 128 + col] - lse);
            }
            if (lane == 0) lseS[i] = lse;
        }
    }
    __syncthreads();

    // overwrite kv with v rows
    for (int idx = tid; idx < 128 * 128; idx += 256) {
        int j = idx >> 7, d = idx & 127;
        kvS[j * 132 + d] = vg[((size_t)(b * T_ + tk[j])) * DIM_ + h * DH_ + d];
    }
    __syncthreads();

    // out = p @ v, scatter to (hash, t) layout
    {
        int it = tid >> 4, jt = tid & 15;
        int i0 = it * 4;
        float acc[4][8];
#pragma unroll
        for (int u = 0; u < 4; u++)
#pragma unroll
            for (int w = 0; w < 8; w++) acc[u][w] = 0.f;
        for (int j = 0; j < 128; j++) {
            float p[4], vv[8];
#pragma unroll
            for (int u = 0; u < 4; u++) p[u] = dots[(i0 + u) * 128 + j];
#pragma unroll
            for (int w = 0; w < 8; w++) vv[w] = kvS[j * 132 + jt + w * 16];
#pragma unroll
            for (int u = 0; u < 4; u++)
#pragma unroll
                for (int w = 0; w < 8; w++) acc[u][w] += p[u] * vv[w];
        }
#pragma unroll
        for (int u = 0; u < 4; u++) {
            int i = i0 + u;
            size_t base = ((size_t)(bh * NHASH_ + hq[i]) * T_ + tq[i]) * DH_;
#pragma unroll
            for (int w = 0; w < 8; w++)
                orounds[base + jt + w * 16] = acc[u][w];
        }
    }
    if (tid < 64) {
        int i = tid;
        lseg[(bh * NHASH_ + hq[i]) * T_ + tq[i]] = lseS[i];
    }
}

// ---------------- combine hash rounds --------------------------------------
__global__ void combine_kernel(const float* __restrict__ orounds, const float* __restrict__ lse,
                               float* __restrict__ attn) {
    int blk = blockIdx.x;                  // bh*T_ + t
    int bh = blk >> 12, t = blk & (T_ - 1);
    int b = bh >> 3, h = bh & 7;
    int d = threadIdx.x;
    float l[4];
#pragma unroll
    for (int hh = 0; hh < 4; hh++) l[hh] = lse[(bh * NHASH_ + hh) * T_ + t];
    float m = fmaxf(fmaxf(l[0], l[1]), fmaxf(l[2], l[3]));
    float s = 0.f;
#pragma unroll
    for (int hh = 0; hh < 4; hh++) s += expf(l[hh] - m);
    float ls = m + logf(s);
    float o = 0.f;
#pragma unroll
    for (int hh = 0; hh < 4; hh++)
        o += expf(l[hh] - ls) * orounds[((size_t)(bh * NHASH_ + hh) * T_ + t) * DH_ + d];
    attn[((size_t)(b * T_ + t)) * DIM_ + h * DH_ + d] = o;
}

// ---------------- final add -------------------------------------------------
__global__ void add_kernel(const float* __restrict__ a, const float* __restrict__ b,
                           float* __restrict__ o, int n) {
    int i = blockIdx.x * blockDim.x + threadIdx.x;
    if (i < n) o[i] = a[i] + b[i];
}

// ---------------- host orchestration ---------------------------------------
extern "C" void kernel_launch(void* const* d_in, const int* in_sizes, int n_in,
                              void* d_out, int out_size) {
    const float* x     = (const float*)d_in[0];
    const float* ln1_g = (const float*)d_in[1];
    const float* ln1_b = (const float*)d_in[2];
    const float* Wqk   = (const float*)d_in[3];
    const float* Wv    = (const float*)d_in[4];
    const float* Wo    = (const float*)d_in[5];
    const float* bo    = (const float*)d_in[6];
    const float* ln2_g = (const float*)d_in[7];
    const float* ln2_b = (const float*)d_in[8];
    const float* W1    = (const float*)d_in[9];
    const float* b1    = (const float*)d_in[10];
    const float* W2    = (const float*)d_in[11];
    const float* b2    = (const float*)d_in[12];
    const float* rot   = (const float*)d_in[13];

    float *x1, *x2, *xn, *qk, *v, *attn, *ff, *orounds, *lse;
    int* keys;
    cudaGetSymbolAddress((void**)&x1, g_x1);
    cudaGetSymbolAddress((void**)&x2, g_x2);
    cudaGetSymbolAddress((void**)&xn, g_xn);
    cudaGetSymbolAddress((void**)&qk, g_qk);
    cudaGetSymbolAddress((void**)&v,  g_v);
    cudaGetSymbolAddress((void**)&attn, g_attn);
    cudaGetSymbolAddress((void**)&ff, g_ff);
    cudaGetSymbolAddress((void**)&orounds, g_orounds);
    cudaGetSymbolAddress((void**)&lse, g_lse);
    cudaGetSymbolAddress((void**)&keys, g_keys);

    cudaFuncSetAttribute(hash_kernel, cudaFuncAttributeMaxDynamicSharedMemorySize, 98304);
    cudaFuncSetAttribute(sort_kernel, cudaFuncAttributeMaxDynamicSharedMemorySize, 65536);
    cudaFuncSetAttribute(attn_kernel, cudaFuncAttributeMaxDynamicSharedMemorySize, 135424);

    size_t bytes = (size_t)BT_ * DIM_ * sizeof(float);
    cudaMemcpyAsync(x1, x, bytes, cudaMemcpyDeviceToDevice, 0);
    cudaMemcpyAsync(x2, x, bytes, cudaMemcpyDeviceToDevice, 0);

    for (int dep = 0; dep < 2; dep++) {
        const float* wqk = Wqk + (size_t)dep * DIM_ * DIM_;
        const float* wv  = Wv  + (size_t)dep * DIM_ * DIM_;
        const float* wo  = Wo  + (size_t)dep * DIM_ * DIM_;
        const float* bov = bo  + (size_t)dep * DIM_;
        const float* w1  = W1  + (size_t)dep * DIM_ * FF_;
        const float* bb1 = b1  + (size_t)dep * FF_;
        const float* w2  = W2  + (size_t)dep * FF_ * DIM_;
        const float* bb2 = b2  + (size_t)dep * DIM_;
        const float* rt  = rot + (size_t)dep * DH_ * NHASH_ * (NB_ / 2);

        ln_kernel<<<BT_, 256>>>(x2, ln1_g + dep * DIM_, ln1_b + dep * DIM_, xn);
        gemm_kernel<<<dim3(DIM_ / 64, BT_ / 64), 256>>>(xn, wqk, nullptr, nullptr, qk, BT_, DIM_, DIM_, 0);
        gemm_kernel<<<dim3(DIM_ / 64, BT_ / 64), 256>>>(xn, wv,  nullptr, nullptr, v,  BT_, DIM_, DIM_, 0);
        hash_kernel<<<BH_ * 64, 256, 98304>>>(qk, rt, keys);
        sort_kernel<<<BH_, 1024, 65536>>>(keys);
        attn_kernel<<<BH_ * NCH_, 256, 135424>>>(qk, v, keys, orounds, lse);
        combine_kernel<<<BH_ * T_, 128>>>(orounds, lse, attn);
        gemm_kernel<<<dim3(DIM_ / 64, BT_ / 64), 256>>>(attn, wo, bov, x1, x1, BT_, DIM_, DIM_, 0);
        ln_kernel<<<BT_, 256>>>(x1, ln2_g + dep * DIM_, ln2_b + dep * DIM_, xn);
        gemm_kernel<<<dim3(FF_ / 64, BT_ / 64), 256>>>(xn, w1, bb1, nullptr, ff, BT_, FF_, DIM_, 1);
        gemm_kernel<<<dim3(DIM_ / 64, BT_ / 64), 256>>>(ff, w2, bb2, x2, x2, BT_, DIM_, FF_, 0);
    }
    add_kernel<<<(BT_ * DIM_ + 255) / 256, 256>>>(x1, x2, (float*)d_out, BT_ * DIM_);
}

// round 4
// speedup vs baseline: 1.8139x; 1.8139x over previous
#include <cuda_runtime.h>
#include <cuda_bf16.h>
#include <math.h>
#include <stdint.h>

#define B_      2
#define T_      4096
#define DIM_    1024
#define HEADS_  8
#define DH_     128
#define NHASH_  4
#define NB_     64
#define BUCKET_ 64
#define BH_     16
#define BT_     8192
#define FF_     4096
#define NCH_    256
#define NSORT_  16384
#define SCALE_  0.08838834764831845f
#define SELF_VAL_ (-5e4f)

// ---------------- scratch ----------------
__device__ float g_x1[BT_*DIM_];
__device__ float g_x2[BT_*DIM_];
__device__ float g_qk[BT_*DIM_];
__device__ float g_v [BT_*DIM_];
__device__ float g_orounds[BH_*NHASH_*T_*DH_];
__device__ float g_lse[BH_*NHASH_*T_];
__device__ int   g_keys[BH_*NSORT_];
// split-bf16 activations (16B-aligned for cp.async)
__device__ __align__(16) __nv_bfloat16 g_xnh[BT_*DIM_], g_xnl[BT_*DIM_];
__device__ __align__(16) __nv_bfloat16 g_ath[BT_*DIM_], g_atl[BT_*DIM_];
__device__ __align__(16) __nv_bfloat16 g_ffh[BT_*FF_],  g_ffl[BT_*FF_];
// transposed split weights [layer][hi/lo][N*K]
__device__ __align__(16) __nv_bfloat16 g_wqkT[2*2*DIM_*DIM_];
__device__ __align__(16) __nv_bfloat16 g_wvT [2*2*DIM_*DIM_];
__device__ __align__(16) __nv_bfloat16 g_woT [2*2*DIM_*DIM_];
__device__ __align__(16) __nv_bfloat16 g_w1T [2*2*FF_*DIM_];
__device__ __align__(16) __nv_bfloat16 g_w2T [2*2*DIM_*FF_];

__device__ __forceinline__ uint32_t smem_u32(const void* p) {
    uint32_t a;
    asm("{ .reg .u64 t; cvta.to.shared.u64 t, %1; cvt.u32.u64 %0, t; }" : "=r"(a) : "l"(p));
    return a;
}
__device__ __forceinline__ void cpa16(uint32_t dst, const void* src) {
    asm volatile("cp.async.cg.shared.global [%0], [%1], 16;" :: "r"(dst), "l"(src));
}
#define CP_COMMIT() asm volatile("cp.async.commit_group;" ::: "memory")
#define LDSM_X4(r0,r1,r2,r3,addr) \
    asm volatile("ldmatrix.sync.aligned.m8n8.x4.shared.b16 {%0,%1,%2,%3}, [%4];" \
        : "=r"(r0), "=r"(r1), "=r"(r2), "=r"(r3) : "r"(addr))
#define LDSM_X2(r0,r1,addr) \
    asm volatile("ldmatrix.sync.aligned.m8n8.x2.shared.b16 {%0,%1}, [%2];" \
        : "=r"(r0), "=r"(r1) : "r"(addr))
#define MMA16816(d, a, b) \
    asm volatile("mma.sync.aligned.m16n8k16.row.col.f32.bf16.bf16.f32 " \
        "{%0,%1,%2,%3}, {%4,%5,%6,%7}, {%8,%9}, {%0,%1,%2,%3};" \
        : "+f"((d)[0]), "+f"((d)[1]), "+f"((d)[2]), "+f"((d)[3]) \
        : "r"((a)[0]), "r"((a)[1]), "r"((a)[2]), "r"((a)[3]), "r"((b)[0]), "r"((b)[1]))

// ================= weight transpose + split =================
__global__ void tsplit_kernel(const float* __restrict__ W, int K, int N,
                              __nv_bfloat16* __restrict__ Thi, __nv_bfloat16* __restrict__ Tlo) {
    __shared__ float tile[32][33];
    int n0 = blockIdx.x * 32, k0 = blockIdx.y * 32;
    int tx = threadIdx.x, ty = threadIdx.y;      // 32 x 8
    for (int r = ty; r < 32; r += 8)
        tile[r][tx] = W[(size_t)(k0 + r) * N + n0 + tx];
    __syncthreads();
    for (int r = ty; r < 32; r += 8) {
        float v = tile[tx][r];
        __nv_bfloat16 hi = __float2bfloat16(v);
        Thi[(size_t)(n0 + r) * K + k0 + tx] = hi;
        Tlo[(size_t)(n0 + r) * K + k0 + tx] = __float2bfloat16(v - __bfloat162float(hi));
    }
}

// ================= layernorm -> split bf16 =================
__global__ void ln_kernel(const float* __restrict__ x, const float* __restrict__ g,
                          const float* __restrict__ bta,
                          __nv_bfloat16* __restrict__ yh, __nv_bfloat16* __restrict__ yl) {
    int row = blockIdx.x;
    int tid = threadIdx.x;
    const float* xr = x + (size_t)row * DIM_;
    float s = 0.f, sq = 0.f;
    for (int d = tid; d < DIM_; d += 256) { float v = xr[d]; s += v; sq += v * v; }
    __shared__ float rs[8], rq[8];
    for (int o = 16; o > 0; o >>= 1) {
        s  += __shfl_down_sync(0xffffffff, s,  o);
        sq += __shfl_down_sync(0xffffffff, sq, o);
    }
    int warp = tid >> 5, lane = tid & 31;
    if (lane == 0) { rs[warp] = s; rq[warp] = sq; }
    __syncthreads();
    if (warp == 0) {
        s  = (lane < 8) ? rs[lane] : 0.f;
        sq = (lane < 8) ? rq[lane] : 0.f;
        for (int o = 4; o > 0; o >>= 1) {
            s  += __shfl_down_sync(0xffffffff, s,  o);
            sq += __shfl_down_sync(0xffffffff, sq, o);
        }
        if (lane == 0) { rs[0] = s; rq[0] = sq; }
    }
    __syncthreads();
    float mean = rs[0] * (1.0f / DIM_);
    float var  = rq[0] * (1.0f / DIM_) - mean * mean;
    float rstd = rsqrtf(var + 1e-5f);
    for (int d = tid; d < DIM_; d += 256) {
        float v = (xr[d] - mean) * rstd * g[d] + bta[d];
        __nv_bfloat16 hi = __float2bfloat16(v);
        yh[(size_t)row * DIM_ + d] = hi;
        yl[(size_t)row * DIM_ + d] = __float2bfloat16(v - __bfloat162float(hi));
    }
}

// ================= mma.sync split-bf16 GEMM =================
// C[M,N] = (Ahi+Alo)[M,K] @ (Bhi+Blo)[N,K]^T, fp32 accum.
// 128x128 tile, 8 warps (2x4), 64x32 per warp, K-chunk 32, 2-stage cp.async.
// Virtual K' = 3K: pass 0 = Ahi*Bhi, pass 1 = Alo*Bhi, pass 2 = Ahi*Blo.
#define PITCH_ 80   // smem row pitch bytes (40 bf16): conflict-free ldmatrix

__global__ void __launch_bounds__(256) gemm_mma(
    const __nv_bfloat16* __restrict__ Ahi, const __nv_bfloat16* __restrict__ Alo,
    const __nv_bfloat16* __restrict__ Bhi, const __nv_bfloat16* __restrict__ Blo,
    const float* __restrict__ bias, const float* __restrict__ resid,
    float* __restrict__ C, __nv_bfloat16* __restrict__ Chi, __nv_bfloat16* __restrict__ Clo,
    int M, int N, int K, int act)
{
    __shared__ __align__(128) char smraw[4 * 128 * PITCH_];  // A0 A1 B0 B1
    uint32_t smA = smem_u32(smraw);
    uint32_t smB = smA + 2 * 128 * PITCH_;
    int tid = threadIdx.x, wid = tid >> 5, lane = tid & 31;
    int m0 = blockIdx.y * 128, n0 = blockIdx.x * 128;
    int m_w = (wid >> 2) * 64, n_w = (wid & 3) * 32;
    int kdiv = K >> 5;
    int nch = 3 * kdiv;

    float acc[4][4][4];
#pragma unroll
    for (int i = 0; i < 4; i++)
#pragma unroll
        for (int j = 0; j < 4; j++)
#pragma unroll
            for (int q = 0; q < 4; q++) acc[i][j][q] = 0.f;

    // lane-invariant pieces of ldmatrix addresses
    int qm = lane >> 3, rm = lane & 7;
    uint32_t a_lane = (uint32_t)(((qm & 1) * 8 + rm) * PITCH_ + (qm >> 1) * 16);
    uint32_t b_lane = (uint32_t)((lane & 7) * PITCH_ + ((lane >> 3) & 1) * 16);

    int ldrow = tid >> 2, ldch = tid & 3;        // loader: 2 rows per thread per tile

    // chunk loader
    auto load_chunk = [&](int c, int buf) {
        int p = c / kdiv;
        int kk = (c - p * kdiv) << 5;
        const __nv_bfloat16* As = (p == 1) ? Alo : Ahi;
        const __nv_bfloat16* Bs = (p == 2) ? Blo : Bhi;
        uint32_t sa = smA + buf * 128 * PITCH_;
        uint32_t sb = smB + buf * 128 * PITCH_;
#pragma unroll
        for (int it = 0; it < 2; it++) {
            int row = ldrow + it * 64;
            uint32_t so = (uint32_t)(row * PITCH_ + ldch * 16);
            cpa16(sa + so, (const char*)(As + (size_t)(m0 + row) * K + kk) + ldch * 16);
            cpa16(sb + so, (const char*)(Bs + (size_t)(n0 + row) * K + kk) + ldch * 16);
        }
        CP_COMMIT();
    };

    load_chunk(0, 0);
    for (int c = 0; c < nch; c++) {
        int buf = c & 1;
        if (c + 1 < nch) {
            load_chunk(c + 1, buf ^ 1);
            asm volatile("cp.async.wait_group 1;" ::: "memory");
        } else {
            asm volatile("cp.async.wait_group 0;" ::: "memory");
        }
        __syncthreads();

        uint32_t aBase = smA + buf * 128 * PITCH_ + m_w * PITCH_ + a_lane;
        uint32_t bBase = smB + buf * 128 * PITCH_ + n_w * PITCH_ + b_lane;
#pragma unroll
        for (int ks = 0; ks < 2; ks++) {
            uint32_t koff = (uint32_t)(ks * 32);
            uint32_t af[4][4], bf[4][2];
#pragma unroll
            for (int mi = 0; mi < 4; mi++)
                LDSM_X4(af[mi][0], af[mi][1], af[mi][2], af[mi][3],
                        aBase + mi * 16 * PITCH_ + koff);
#pragma unroll
            for (int ni = 0; ni < 4; ni++)
                LDSM_X2(bf[ni][0], bf[ni][1], bBase + ni * 8 * PITCH_ + koff);
#pragma unroll
            for (int mi = 0; mi < 4; mi++)
#pragma unroll
                for (int ni = 0; ni < 4; ni++)
                    MMA16816(acc[mi][ni], af[mi], bf[ni]);
        }
        __syncthreads();
    }

    // epilogue
    int grp = lane >> 2, qd = lane & 3;
#pragma unroll
    for (int mi = 0; mi < 4; mi++) {
#pragma unroll
        for (int half = 0; half < 2; half++) {
            int row = m0 + m_w + mi * 16 + grp + half * 8;
#pragma unroll
            for (int ni = 0; ni < 4; ni++) {
                int col = n0 + n_w + ni * 8 + qd * 2;
                float v0 = acc[mi][ni][half * 2 + 0];
                float v1 = acc[mi][ni][half * 2 + 1];
                if (bias) { v0 += bias[col]; v1 += bias[col + 1]; }
                if (act) {
                    v0 = 0.5f * v0 * (1.0f + erff(v0 * 0.70710678118654752f));
                    v1 = 0.5f * v1 * (1.0f + erff(v1 * 0.70710678118654752f));
                }
                if (resid) {
                    const float2 rr = *(const float2*)&resid[(size_t)row * N + col];
                    v0 += rr.x; v1 += rr.y;
                }
                if (C) {
                    float2 o; o.x = v0; o.y = v1;
                    *(float2*)&C[(size_t)row * N + col] = o;
                }
                if (Chi) {
                    __nv_bfloat162 h2, l2;
                    h2.x = __float2bfloat16(v0); h2.y = __float2bfloat16(v1);
                    l2.x = __float2bfloat16(v0 - __bfloat162float(h2.x));
                    l2.y = __float2bfloat16(v1 - __bfloat162float(h2.y));
                    *(__nv_bfloat162*)&Chi[(size_t)row * N + col] = h2;
                    *(__nv_bfloat162*)&Clo[(size_t)row * N + col] = l2;
                }
            }
        }
    }
}

// ================= LSH hashing =================
__global__ void hash_kernel(const float* __restrict__ qk, const float* __restrict__ rot,
                            int* __restrict__ keys) {
    extern __shared__ float sm[];
    float* rotS = sm;
    float* qS   = sm + 16384;
    int bh = blockIdx.x >> 6;
    int tile = blockIdx.x & 63;
    int b = bh >> 3, h = bh & 7;
    int tid = threadIdx.x;
    for (int idx = tid; idx < 16384; idx += 256) rotS[idx] = rot[idx];
    int t0 = tile * 64;
    for (int idx = tid; idx < 8192; idx += 256) {
        int tok = idx >> 7, d = idx & 127;
        qS[idx] = qk[((size_t)(b * T_ + t0 + tok)) * DIM_ + h * DH_ + d];
    }
    __syncthreads();
    int tg = tid >> 7;
    int combo = tid & 127;
    int hh = combo >> 5, i = combo & 31;
    for (int pass = 0; pass < 4; pass++) {
        int base = (pass * 2 + tg) * 8;
        float acc[8];
#pragma unroll
        for (int u = 0; u < 8; u++) acc[u] = 0.f;
        for (int d = 0; d < 128; d++) {
            float rv = rotS[(d * 4 + hh) * 32 + i];
#pragma unroll
            for (int u = 0; u < 8; u++) acc[u] += qS[(base + u) * 128 + d] * rv;
        }
#pragma unroll
        for (int u = 0; u < 8; u++) {
            float v; int idx;
            if (acc[u] >= -acc[u]) { v = acc[u];  idx = i; }
            else                   { v = -acc[u]; idx = i + 32; }
            for (int o = 16; o > 0; o >>= 1) {
                float ov = __shfl_down_sync(0xffffffff, v, o);
                int   oi = __shfl_down_sync(0xffffffff, idx, o);
                if (ov > v || (ov == v && oi < idx)) { v = ov; idx = oi; }
            }
            if (i == 0) {
                int t = t0 + base + u;
                int bucket = idx + hh * NB_;
                keys[bh * NSORT_ + hh * T_ + t] = bucket * T_ + t;
            }
        }
    }
}

// ================= per-round bitonic sort (4096 keys/segment) =============
__global__ void sort_kernel(int* __restrict__ keys) {
    __shared__ int sk[4096];
    int seg = blockIdx.x;
    int* g = keys + (size_t)seg * 4096;
    int tid = threadIdx.x;                // 1024
    for (int i = tid; i < 4096; i += 1024) sk[i] = g[i];
    __syncthreads();
    for (int k = 2; k <= 4096; k <<= 1) {
        for (int j = k >> 1; j > 0; j >>= 1) {
            for (int i = tid; i < 4096; i += 1024) {
                int ixj = i ^ j;
                if (ixj > i) {
                    int a = sk[i], c = sk[ixj];
                    bool up = ((i & k) == 0);
                    if ((a > c) == up) { sk[i] = c; sk[ixj] = a; }
                }
            }
            __syncthreads();
        }
    }
    for (int i = tid; i < 4096; i += 1024) g[i] = sk[i];
}

// ================= chunked attention =================
__global__ void attn_kernel(const float* __restrict__ qk, const float* __restrict__ vg,
                            const int* __restrict__ keys, float* __restrict__ orounds,
                            float* __restrict__ lseg) {
    extern __shared__ float sm[];
    float* qS   = sm;
    float* kvS  = qS + 64 * 132;
    float* dots = kvS + 128 * 132;
    float* lseS = dots + 64 * 128;
    int*   tq   = (int*)(lseS + 64);
    int*   hq   = tq + 64;
    int*   tk   = hq + 64;

    int blk = blockIdx.x;
    int bh = blk >> 8;
    int c  = blk & 255;
    int cp = (c + NCH_ - 1) & 255;
    int b = bh >> 3, h = bh & 7;
    int tid = threadIdx.x;

    if (tid < 128) {
        int j = tid;
        int ch = (j < 64) ? c : cp;
        int p = ch * 64 + (j & 63);
        int key = keys[bh * NSORT_ + p];
        int t = key & (T_ - 1);
        tk[j] = t;
        if (j < 64) { tq[j] = t; hq[j] = key >> 18; }
    }
    __syncthreads();

    for (int idx = tid; idx < 64 * 128; idx += 256) {
        int i = idx >> 7, d = idx & 127;
        qS[i * 132 + d] = qk[((size_t)(b * T_ + tq[i])) * DIM_ + h * DH_ + d];
    }
    for (int idx = tid; idx < 128 * 128; idx += 256) {
        int j = idx >> 7, d = idx & 127;
        kvS[j * 132 + d] = qk[((size_t)(b * T_ + tk[j])) * DIM_ + h * DH_ + d];
    }
    __syncthreads();

    if (tid < 128) {
        float ss = 0.f;
        for (int d = 0; d < 128; d++) { float v = kvS[tid * 132 + d]; ss += v * v; }
        float inv = 1.0f / fmaxf(sqrtf(ss), 1e-12f);
        for (int d = 0; d < 128; d++) kvS[tid * 132 + d] *= inv;
    }
    __syncthreads();

    {
        int it = tid >> 4, jt = tid & 15;
        int i0 = it * 4;
        float acc[4][8];
#pragma unroll
        for (int u = 0; u < 4; u++)
#pragma unroll
            for (int w = 0; w < 8; w++) acc[u][w] = 0.f;
        for (int d = 0; d < 128; d++) {
            float a[4], bb[8];
#pragma unroll
            for (int u = 0; u < 4; u++) a[u] = qS[(i0 + u) * 132 + d];
#pragma unroll
            for (int w = 0; w < 8; w++) bb[w] = kvS[(jt + w * 16) * 132 + d];
#pragma unroll
            for (int u = 0; u < 4; u++)
#pragma unroll
                for (int w = 0; w < 8; w++) acc[u][w] += a[u] * bb[w];
        }
#pragma unroll
        for (int u = 0; u < 4; u++) {
            int ti = tq[i0 + u];
#pragma unroll
            for (int w = 0; w < 8; w++) {
                int j = jt + w * 16;
                float v = (ti == tk[j]) ? SELF_VAL_ : acc[u][w] * SCALE_;
                dots[(i0 + u) * 128 + j] = v;
            }
        }
    }
    __syncthreads();

    {
        int warp = tid >> 5, lane = tid & 31;
        for (int rr = 0; rr < 8; rr++) {
            int i = warp * 8 + rr;
            float m = -3.0e38f;
#pragma unroll
            for (int u = 0; u < 4; u++) m = fmaxf(m, dots[i * 128 + lane + u * 32]);
            for (int o = 16; o > 0; o >>= 1) m = fmaxf(m, __shfl_xor_sync(0xffffffff, m, o));
            float s = 0.f;
#pragma unroll
            for (int u = 0; u < 4; u++) s += expf(dots[i * 128 + lane + u * 32] - m);
            for (int o = 16; o > 0; o >>= 1) s += __shfl_xor_sync(0xffffffff, s, o);
            float lse = m + logf(s);
#pragma unroll
            for (int u = 0; u < 4; u++) {
                int col = lane + u * 32;
                dots[i * 128 + col] = expf(dots[i * 128 + col] - lse);
            }
            if (lane == 0) lseS[i] = lse;
        }
    }
    __syncthreads();

    for (int idx = tid; idx < 128 * 128; idx += 256) {
        int j = idx >> 7, d = idx & 127;
        kvS[j * 132 + d] = vg[((size_t)(b * T_ + tk[j])) * DIM_ + h * DH_ + d];
    }
    __syncthreads();

    {
        int it = tid >> 4, jt = tid & 15;
        int i0 = it * 4;
        float acc[4][8];
#pragma unroll
        for (int u = 0; u < 4; u++)
#pragma unroll
            for (int w = 0; w < 8; w++) acc[u][w] = 0.f;
        for (int j = 0; j < 128; j++) {
            float p[4], vv[8];
#pragma unroll
            for (int u = 0; u < 4; u++) p[u] = dots[(i0 + u) * 128 + j];
#pragma unroll
            for (int w = 0; w < 8; w++) vv[w] = kvS[j * 132 + jt + w * 16];
#pragma unroll
            for (int u = 0; u < 4; u++)
#pragma unroll
                for (int w = 0; w < 8; w++) acc[u][w] += p[u] * vv[w];
        }
#pragma unroll
        for (int u = 0; u < 4; u++) {
            int i = i0 + u;
            size_t base = ((size_t)(bh * NHASH_ + hq[i]) * T_ + tq[i]) * DH_;
#pragma unroll
            for (int w = 0; w < 8; w++)
                orounds[base + jt + w * 16] = acc[u][w];
        }
    }
    if (tid < 64) {
        int i = tid;
        lseg[(bh * NHASH_ + hq[i]) * T_ + tq[i]] = lseS[i];
    }
}

// ================= combine hash rounds -> split bf16 =================
__global__ void combine_kernel(const float* __restrict__ orounds, const float* __restrict__ lse,
                               __nv_bfloat16* __restrict__ ah, __nv_bfloat16* __restrict__ al) {
    int blk = blockIdx.x;
    int bh = blk >> 12, t = blk & (T_ - 1);
    int b = bh >> 3, h = bh & 7;
    int d = threadIdx.x;
    float l[4];
#pragma unroll
    for (int hh = 0; hh < 4; hh++) l[hh] = lse[(bh * NHASH_ + hh) * T_ + t];
    float m = fmaxf(fmaxf(l[0], l[1]), fmaxf(l[2], l[3]));
    float s = 0.f;
#pragma unroll
    for (int hh = 0; hh < 4; hh++) s += expf(l[hh] - m);
    float ls = m + logf(s);
    float o = 0.f;
#pragma unroll
    for (int hh = 0; hh < 4; hh++)
        o += expf(l[hh] - ls) * orounds[((size_t)(bh * NHASH_ + hh) * T_ + t) * DH_ + d];
    size_t oi = ((size_t)(b * T_ + t)) * DIM_ + h * DH_ + d;
    __nv_bfloat16 hi = __float2bfloat16(o);
    ah[oi] = hi;
    al[oi] = __float2bfloat16(o - __bfloat162float(hi));
}

__global__ void add_kernel(const float* __restrict__ a, const float* __restrict__ b,
                           float* __restrict__ o, int n) {
    int i = blockIdx.x * blockDim.x + threadIdx.x;
    if (i < n) o[i] = a[i] + b[i];
}

// ================= host =================
extern "C" void kernel_launch(void* const* d_in, const int* in_sizes, int n_in,
                              void* d_out, int out_size) {
    const float* x     = (const float*)d_in[0];
    const float* ln1_g = (const float*)d_in[1];
    const float* ln1_b = (const float*)d_in[2];
    const float* Wqk   = (const float*)d_in[3];
    const float* Wv    = (const float*)d_in[4];
    const float* Wo    = (const float*)d_in[5];
    const float* bo    = (const float*)d_in[6];
    const float* ln2_g = (const float*)d_in[7];
    const float* ln2_b = (const float*)d_in[8];
    const float* W1    = (const float*)d_in[9];
    const float* b1    = (const float*)d_in[10];
    const float* W2    = (const float*)d_in[11];
    const float* b2    = (const float*)d_in[12];
    const float* rot   = (const float*)d_in[13];

    float *x1, *x2, *qk, *v, *orounds, *lse;
    int* keys;
    __nv_bfloat16 *xnh, *xnl, *ath, *atl, *ffh, *ffl;
    __nv_bfloat16 *wqkT, *wvT, *woT, *w1T, *w2T;
    cudaGetSymbolAddress((void**)&x1, g_x1);
    cudaGetSymbolAddress((void**)&x2, g_x2);
    cudaGetSymbolAddress((void**)&qk, g_qk);
    cudaGetSymbolAddress((void**)&v,  g_v);
    cudaGetSymbolAddress((void**)&orounds, g_orounds);
    cudaGetSymbolAddress((void**)&lse, g_lse);
    cudaGetSymbolAddress((void**)&keys, g_keys);
    cudaGetSymbolAddress((void**)&xnh, g_xnh);
    cudaGetSymbolAddress((void**)&xnl, g_xnl);
    cudaGetSymbolAddress((void**)&ath, g_ath);
    cudaGetSymbolAddress((void**)&atl, g_atl);
    cudaGetSymbolAddress((void**)&ffh, g_ffh);
    cudaGetSymbolAddress((void**)&ffl, g_ffl);
    cudaGetSymbolAddress((void**)&wqkT, g_wqkT);
    cudaGetSymbolAddress((void**)&wvT,  g_wvT);
    cudaGetSymbolAddress((void**)&woT,  g_woT);
    cudaGetSymbolAddress((void**)&w1T,  g_w1T);
    cudaGetSymbolAddress((void**)&w2T,  g_w2T);

    cudaFuncSetAttribute(hash_kernel, cudaFuncAttributeMaxDynamicSharedMemorySize, 98304);
    cudaFuncSetAttribute(attn_kernel, cudaFuncAttributeMaxDynamicSharedMemorySize, 135424);

    size_t bytes = (size_t)BT_ * DIM_ * sizeof(float);
    cudaMemcpyAsync(x1, x, bytes, cudaMemcpyDeviceToDevice, 0);
    cudaMemcpyAsync(x2, x, bytes, cudaMemcpyDeviceToDevice, 0);

    for (int dep = 0; dep < 2; dep++) {
        size_t o1 = (size_t)dep * 2 * DIM_ * DIM_;
        size_t o4 = (size_t)dep * 2 * FF_ * DIM_;
        tsplit_kernel<<<dim3(32, 32), dim3(32, 8)>>>(Wqk + (size_t)dep*DIM_*DIM_, DIM_, DIM_,
                                                     wqkT + o1, wqkT + o1 + DIM_*DIM_);
        tsplit_kernel<<<dim3(32, 32), dim3(32, 8)>>>(Wv  + (size_t)dep*DIM_*DIM_, DIM_, DIM_,
                                                     wvT + o1, wvT + o1 + DIM_*DIM_);
        tsplit_kernel<<<dim3(32, 32), dim3(32, 8)>>>(Wo  + (size_t)dep*DIM_*DIM_, DIM_, DIM_,
                                                     woT + o1, woT + o1 + DIM_*DIM_);
        tsplit_kernel<<<dim3(128, 32), dim3(32, 8)>>>(W1 + (size_t)dep*DIM_*FF_, DIM_, FF_,
                                                      w1T + o4, w1T + o4 + (size_t)FF_*DIM_);
        tsplit_kernel<<<dim3(32, 128), dim3(32, 8)>>>(W2 + (size_t)dep*FF_*DIM_, FF_, DIM_,
                                                      w2T + o4, w2T + o4 + (size_t)FF_*DIM_);
    }

    for (int dep = 0; dep < 2; dep++) {
        size_t o1 = (size_t)dep * 2 * DIM_ * DIM_;
        size_t o4 = (size_t)dep * 2 * FF_ * DIM_;
        const float* bov = bo + (size_t)dep * DIM_;
        const float* bb1 = b1 + (size_t)dep * FF_;
        const float* bb2 = b2 + (size_t)dep * DIM_;
        const float* rt  = rot + (size_t)dep * DH_ * NHASH_ * (NB_ / 2);

        ln_kernel<<<BT_, 256>>>(x2, ln1_g + dep * DIM_, ln1_b + dep * DIM_, xnh, xnl);
        gemm_mma<<<dim3(8, 64), 256>>>(xnh, xnl, wqkT + o1, wqkT + o1 + DIM_*DIM_,
                                       nullptr, nullptr, qk, nullptr, nullptr,
                                       BT_, DIM_, DIM_, 0);
        gemm_mma<<<dim3(8, 64), 256>>>(xnh, xnl, wvT + o1, wvT + o1 + DIM_*DIM_,
                                       nullptr, nullptr, v, nullptr, nullptr,
                                       BT_, DIM_, DIM_, 0);
        hash_kernel<<<BH_ * 64, 256, 98304>>>(qk, rt, keys);
        sort_kernel<<<BH_ * NHASH_, 1024>>>(keys);
        attn_kernel<<<BH_ * NCH_, 256, 135424>>>(qk, v, keys, orounds, lse);
        combine_kernel<<<BH_ * T_, 128>>>(orounds, lse, ath, atl);
        gemm_mma<<<dim3(8, 64), 256>>>(ath, atl, woT + o1, woT + o1 + DIM_*DIM_,
                                       bov, x1, x1, nullptr, nullptr,
                                       BT_, DIM_, DIM_, 0);
        ln_kernel<<<BT_, 256>>>(x1, ln2_g + dep * DIM_, ln2_b + dep * DIM_, xnh, xnl);
        gemm_mma<<<dim3(32, 64), 256>>>(xnh, xnl, w1T + o4, w1T + o4 + (size_t)FF_*DIM_,
                                        bb1, nullptr, nullptr, ffh, ffl,
                                        BT_, FF_, DIM_, 1);
        gemm_mma<<<dim3(8, 64), 256>>>(ffh, ffl, w2T + o4, w2T + o4 + (size_t)FF_*DIM_,
                                       bb2, x2, x2, nullptr, nullptr,
                                       BT_, DIM_, FF_, 0);
    }
    add_kernel<<<(BT_ * DIM_ + 255) / 256, 256>>>(x1, x2, (float*)d_out, BT_ * DIM_);
}

// round 7
// speedup vs baseline: 1.9741x; 1.0883x over previous
#include <cuda_runtime.h>
#include <cuda_bf16.h>
#include <math.h>
#include <stdint.h>

#define B_      2
#define T_      4096
#define DIM_    1024
#define HEADS_  8
#define DH_     128
#define NHASH_  4
#define NB_     64
#define BUCKET_ 64
#define BH_     16
#define BT_     8192
#define FF_     4096
#define NCH_    256
#define NSORT_  16384
#define SCALE_  0.08838834764831845f
#define SELF_VAL_ (-5e4f)

// ---------------- scratch ----------------
__device__ float g_x1[BT_*DIM_];
__device__ float g_x2[BT_*DIM_];
__device__ float g_qk[BT_*DIM_];
__device__ float g_v [BT_*DIM_];
__device__ float g_orounds[BH_*NHASH_*T_*DH_];
__device__ float g_lse[BH_*NHASH_*T_];
__device__ int   g_keys[BH_*NSORT_];
__device__ __align__(16) __nv_bfloat16 g_xnh[BT_*DIM_], g_xnl[BT_*DIM_];
__device__ __align__(16) __nv_bfloat16 g_ath[BT_*DIM_], g_atl[BT_*DIM_];
__device__ __align__(16) __nv_bfloat16 g_ffh[BT_*FF_],  g_ffl[BT_*FF_];
__device__ __align__(16) __nv_bfloat16 g_wqkT[2*2*DIM_*DIM_];
__device__ __align__(16) __nv_bfloat16 g_wvT [2*2*DIM_*DIM_];
__device__ __align__(16) __nv_bfloat16 g_woT [2*2*DIM_*DIM_];
__device__ __align__(16) __nv_bfloat16 g_w1T [2*2*FF_*DIM_];
__device__ __align__(16) __nv_bfloat16 g_w2T [2*2*DIM_*FF_];

__device__ __forceinline__ uint32_t smem_u32(const void* p) {
    uint32_t a;
    asm("{ .reg .u64 t; cvta.to.shared.u64 t, %1; cvt.u32.u64 %0, t; }" : "=r"(a) : "l"(p));
    return a;
}
__device__ __forceinline__ void cpa16(uint32_t dst, const void* src) {
    asm volatile("cp.async.cg.shared.global [%0], [%1], 16;" :: "r"(dst), "l"(src));
}
#define CP_COMMIT() asm volatile("cp.async.commit_group;" ::: "memory")
#define CP_WAIT1()  asm volatile("cp.async.wait_group 1;" ::: "memory")
#define LDSM_X4(r0,r1,r2,r3,addr) \
    asm volatile("ldmatrix.sync.aligned.m8n8.x4.shared.b16 {%0,%1,%2,%3}, [%4];" \
        : "=r"(r0), "=r"(r1), "=r"(r2), "=r"(r3) : "r"(addr))
#define LDSM_X2(r0,r1,addr) \
    asm volatile("ldmatrix.sync.aligned.m8n8.x2.shared.b16 {%0,%1}, [%2];" \
        : "=r"(r0), "=r"(r1) : "r"(addr))
#define MMA16816(d, a, b) \
    asm volatile("mma.sync.aligned.m16n8k16.row.col.f32.bf16.bf16.f32 " \
        "{%0,%1,%2,%3}, {%4,%5,%6,%7}, {%8,%9}, {%0,%1,%2,%3};" \
        : "+f"((d)[0]), "+f"((d)[1]), "+f"((d)[2]), "+f"((d)[3]) \
        : "r"((a)[0]), "r"((a)[1]), "r"((a)[2]), "r"((a)[3]), "r"((b)[0]), "r"((b)[1]))

// ================= weight transpose + split =================
__global__ void tsplit_kernel(const float* __restrict__ W, int K, int N,
                              __nv_bfloat16* __restrict__ Thi, __nv_bfloat16* __restrict__ Tlo) {
    __shared__ float tile[32][33];
    int n0 = blockIdx.x * 32, k0 = blockIdx.y * 32;
    int tx = threadIdx.x, ty = threadIdx.y;
    for (int r = ty; r < 32; r += 8)
        tile[r][tx] = W[(size_t)(k0 + r) * N + n0 + tx];
    __syncthreads();
    for (int r = ty; r < 32; r += 8) {
        float v = tile[tx][r];
        __nv_bfloat16 hi = __float2bfloat16(v);
        Thi[(size_t)(n0 + r) * K + k0 + tx] = hi;
        Tlo[(size_t)(n0 + r) * K + k0 + tx] = __float2bfloat16(v - __bfloat162float(hi));
    }
}

// ================= layernorm -> split bf16 =================
__global__ void ln_kernel(const float* __restrict__ x, const float* __restrict__ g,
                          const float* __restrict__ bta,
                          __nv_bfloat16* __restrict__ yh, __nv_bfloat16* __restrict__ yl) {
    int row = blockIdx.x;
    int tid = threadIdx.x;
    const float* xr = x + (size_t)row * DIM_;
    float s = 0.f, sq = 0.f;
    for (int d = tid; d < DIM_; d += 256) { float v = xr[d]; s += v; sq += v * v; }
    __shared__ float rs[8], rq[8];
    for (int o = 16; o > 0; o >>= 1) {
        s  += __shfl_down_sync(0xffffffff, s,  o);
        sq += __shfl_down_sync(0xffffffff, sq, o);
    }
    int warp = tid >> 5, lane = tid & 31;
    if (lane == 0) { rs[warp] = s; rq[warp] = sq; }
    __syncthreads();
    if (warp == 0) {
        s  = (lane < 8) ? rs[lane] : 0.f;
        sq = (lane < 8) ? rq[lane] : 0.f;
        for (int o = 4; o > 0; o >>= 1) {
            s  += __shfl_down_sync(0xffffffff, s,  o);
            sq += __shfl_down_sync(0xffffffff, sq, o);
        }
        if (lane == 0) { rs[0] = s; rq[0] = sq; }
    }
    __syncthreads();
    float mean = rs[0] * (1.0f / DIM_);
    float var  = rq[0] * (1.0f / DIM_) - mean * mean;
    float rstd = rsqrtf(var + 1e-5f);
    for (int d = tid; d < DIM_; d += 256) {
        float v = (xr[d] - mean) * rstd * g[d] + bta[d];
        __nv_bfloat16 hi = __float2bfloat16(v);
        yh[(size_t)row * DIM_ + d] = hi;
        yl[(size_t)row * DIM_ + d] = __float2bfloat16(v - __bfloat162float(hi));
    }
}

// ================= multistage mma.sync split-bf16 GEMM =================
// C[M,N] = sum over passes of Ap[M,K] @ Bp[N,K]^T, fp32 accum.
// 128x128 tile, 8 warps (2x4), 64x32/warp, K-chunk 64, 3-stage cp.async.
// Passes: 0 hi*hi, 1 lo*hi, 2 hi*lo, (3 lo*lo if npass==4).
#define PITCH_ 144                         // bytes per 64-bf16 row (conflict-free)
#define STAGE_ (2 * 128 * PITCH_)          // A + B per stage = 36864
#define GSMEM_ (3 * STAGE_)                // 110592

__global__ void __launch_bounds__(256) gemm_mma(
    const __nv_bfloat16* __restrict__ Ahi, const __nv_bfloat16* __restrict__ Alo,
    const __nv_bfloat16* __restrict__ Bhi, const __nv_bfloat16* __restrict__ Blo,
    const float* __restrict__ bias, const float* __restrict__ resid,
    float* __restrict__ C, __nv_bfloat16* __restrict__ Chi, __nv_bfloat16* __restrict__ Clo,
    int M, int N, int K, int act, int npass)
{
    extern __shared__ __align__(128) char smraw[];
    uint32_t sm0 = smem_u32(smraw);
    int tid = threadIdx.x, wid = tid >> 5, lane = tid & 31;
    int m0 = blockIdx.y * 128, n0 = blockIdx.x * 128;
    int m_w = (wid >> 2) * 64, n_w = (wid & 3) * 32;
    int kdiv = K >> 6;
    int nch = npass * kdiv;

    float acc[4][4][4];
#pragma unroll
    for (int i = 0; i < 4; i++)
#pragma unroll
        for (int j = 0; j < 4; j++)
#pragma unroll
            for (int q = 0; q < 4; q++) acc[i][j][q] = 0.f;

    int qm = lane >> 3, rm = lane & 7;
    uint32_t a_lane = (uint32_t)(((qm & 1) * 8 + rm) * PITCH_ + (qm >> 1) * 16);
    uint32_t b_lane = (uint32_t)((lane & 7) * PITCH_ + ((lane >> 3) & 1) * 16);

    // loader: 4 x 16B for A, 4 x 16B for B per thread
    auto load_chunk = [&](int c, int stg) {
        int p = c / kdiv;
        int kk = (c - p * kdiv) << 6;                 // element offset in K
        const __nv_bfloat16* As = (p & 1) ? Alo : Ahi;
        const __nv_bfloat16* Bs = (p >> 1) ? Blo : Bhi;
        uint32_t sa = sm0 + stg * STAGE_;
        uint32_t sb = sa + 128 * PITCH_;
        const char* ga = (const char*)As + ((size_t)m0 * K + kk) * 2;
        const char* gb = (const char*)Bs + ((size_t)n0 * K + kk) * 2;
        size_t gp = (size_t)K * 2;
#pragma unroll
        for (int it = 0; it < 4; it++) {
            int idx = tid + it * 256;
            int row = idx >> 3, ch = idx & 7;
            uint32_t so = (uint32_t)(row * PITCH_ + ch * 16);
            cpa16(sa + so, ga + (size_t)row * gp + ch * 16);
            cpa16(sb + so, gb + (size_t)row * gp + ch * 16);
        }
        CP_COMMIT();
    };

    load_chunk(0, 0);
    load_chunk(1, 1);
    int stg = 0;
    for (int c = 0; c < nch; c++) {
        CP_WAIT1();
        __syncthreads();
        if (c + 2 < nch) load_chunk(c + 2, (stg + 2) % 3);
        else CP_COMMIT();                               // keep group count uniform

        uint32_t aBase = sm0 + stg * STAGE_ + m_w * PITCH_ + a_lane;
        uint32_t bBase = sm0 + stg * STAGE_ + 128 * PITCH_ + n_w * PITCH_ + b_lane;
#pragma unroll
        for (int ks = 0; ks < 4; ks++) {
            uint32_t koff = (uint32_t)(ks * 32);
            uint32_t af[4][4], bf[4][2];
#pragma unroll
            for (int mi = 0; mi < 4; mi++)
                LDSM_X4(af[mi][0], af[mi][1], af[mi][2], af[mi][3],
                        aBase + mi * 16 * PITCH_ + koff);
#pragma unroll
            for (int ni = 0; ni < 4; ni++)
                LDSM_X2(bf[ni][0], bf[ni][1], bBase + ni * 8 * PITCH_ + koff);
#pragma unroll
            for (int mi = 0; mi < 4; mi++)
#pragma unroll
                for (int ni = 0; ni < 4; ni++)
                    MMA16816(acc[mi][ni], af[mi], bf[ni]);
        }
        stg = (stg + 1) % 3;
    }

    // epilogue
    int grp = lane >> 2, qd = lane & 3;
#pragma unroll
    for (int mi = 0; mi < 4; mi++) {
#pragma unroll
        for (int half = 0; half < 2; half++) {
            int row = m0 + m_w + mi * 16 + grp + half * 8;
#pragma unroll
            for (int ni = 0; ni < 4; ni++) {
                int col = n0 + n_w + ni * 8 + qd * 2;
                float v0 = acc[mi][ni][half * 2 + 0];
                float v1 = acc[mi][ni][half * 2 + 1];
                if (bias) { v0 += bias[col]; v1 += bias[col + 1]; }
                if (act) {
                    v0 = 0.5f * v0 * (1.0f + erff(v0 * 0.70710678118654752f));
                    v1 = 0.5f * v1 * (1.0f + erff(v1 * 0.70710678118654752f));
                }
                if (resid) {
                    const float2 rr = *(const float2*)&resid[(size_t)row * N + col];
                    v0 += rr.x; v1 += rr.y;
                }
                if (C) {
                    float2 o; o.x = v0; o.y = v1;
                    *(float2*)&C[(size_t)row * N + col] = o;
                }
                if (Chi) {
                    __nv_bfloat162 h2, l2;
                    h2.x = __float2bfloat16(v0); h2.y = __float2bfloat16(v1);
                    l2.x = __float2bfloat16(v0 - __bfloat162float(h2.x));
                    l2.y = __float2bfloat16(v1 - __bfloat162float(h2.y));
                    *(__nv_bfloat162*)&Chi[(size_t)row * N + col] = h2;
                    *(__nv_bfloat162*)&Clo[(size_t)row * N + col] = l2;
                }
            }
        }
    }
}

// ================= LSH hashing =================
__global__ void hash_kernel(const float* __restrict__ qk, const float* __restrict__ rot,
                            int* __restrict__ keys) {
    extern __shared__ float sm[];
    float* rotS = sm;
    float* qS   = sm + 16384;
    int bh = blockIdx.x >> 6;
    int tile = blockIdx.x & 63;
    int b = bh >> 3, h = bh & 7;
    int tid = threadIdx.x;
    for (int idx = tid; idx < 16384; idx += 256) rotS[idx] = rot[idx];
    int t0 = tile * 64;
    for (int idx = tid; idx < 8192; idx += 256) {
        int tok = idx >> 7, d = idx & 127;
        qS[idx] = qk[((size_t)(b * T_ + t0 + tok)) * DIM_ + h * DH_ + d];
    }
    __syncthreads();
    int tg = tid >> 7;
    int combo = tid & 127;
    int hh = combo >> 5, i = combo & 31;
    for (int pass = 0; pass < 4; pass++) {
        int base = (pass * 2 + tg) * 8;
        float acc[8];
#pragma unroll
        for (int u = 0; u < 8; u++) acc[u] = 0.f;
        for (int d = 0; d < 128; d++) {
            float rv = rotS[(d * 4 + hh) * 32 + i];
#pragma unroll
            for (int u = 0; u < 8; u++) acc[u] += qS[(base + u) * 128 + d] * rv;
        }
#pragma unroll
        for (int u = 0; u < 8; u++) {
            float v; int idx;
            if (acc[u] >= -acc[u]) { v = acc[u];  idx = i; }
            else                   { v = -acc[u]; idx = i + 32; }
            for (int o = 16; o > 0; o >>= 1) {
                float ov = __shfl_down_sync(0xffffffff, v, o);
                int   oi = __shfl_down_sync(0xffffffff, idx, o);
                if (ov > v || (ov == v && oi < idx)) { v = ov; idx = oi; }
            }
            if (i == 0) {
                int t = t0 + base + u;
                int bucket = idx + hh * NB_;
                keys[bh * NSORT_ + hh * T_ + t] = bucket * T_ + t;
            }
        }
    }
}

// ================= per-round bitonic sort =================
__global__ void sort_kernel(int* __restrict__ keys) {
    __shared__ int sk[4096];
    int seg = blockIdx.x;
    int* g = keys + (size_t)seg * 4096;
    int tid = threadIdx.x;
    for (int i = tid; i < 4096; i += 1024) sk[i] = g[i];
    __syncthreads();
    for (int k = 2; k <= 4096; k <<= 1) {
        for (int j = k >> 1; j > 0; j >>= 1) {
            for (int i = tid; i < 4096; i += 1024) {
                int ixj = i ^ j;
                if (ixj > i) {
                    int a = sk[i], c = sk[ixj];
                    bool up = ((i & k) == 0);
                    if ((a > c) == up) { sk[i] = c; sk[ixj] = a; }
                }
            }
            __syncthreads();
        }
    }
    for (int i = tid; i < 4096; i += 1024) g[i] = sk[i];
}

// ================= chunked attention =================
__global__ void attn_kernel(const float* __restrict__ qk, const float* __restrict__ vg,
                            const int* __restrict__ keys, float* __restrict__ orounds,
                            float* __restrict__ lseg) {
    extern __shared__ float sm[];
    float* qS   = sm;
    float* kvS  = qS + 64 * 132;
    float* dots = kvS + 128 * 132;
    float* lseS = dots + 64 * 128;
    int*   tq   = (int*)(lseS + 64);
    int*   hq   = tq + 64;
    int*   tk   = hq + 64;

    int blk = blockIdx.x;
    int bh = blk >> 8;
    int c  = blk & 255;
    int cp = (c + NCH_ - 1) & 255;
    int b = bh >> 3, h = bh & 7;
    int tid = threadIdx.x;

    if (tid < 128) {
        int j = tid;
        int ch = (j < 64) ? c : cp;
        int p = ch * 64 + (j & 63);
        int key = keys[bh * NSORT_ + p];
        int t = key & (T_ - 1);
        tk[j] = t;
        if (j < 64) { tq[j] = t; hq[j] = key >> 18; }
    }
    __syncthreads();

    for (int idx = tid; idx < 64 * 128; idx += 256) {
        int i = idx >> 7, d = idx & 127;
        qS[i * 132 + d] = qk[((size_t)(b * T_ + tq[i])) * DIM_ + h * DH_ + d];
    }
    for (int idx = tid; idx < 128 * 128; idx += 256) {
        int j = idx >> 7, d = idx & 127;
        kvS[j * 132 + d] = qk[((size_t)(b * T_ + tk[j])) * DIM_ + h * DH_ + d];
    }
    __syncthreads();

    if (tid < 128) {
        float ss = 0.f;
        for (int d = 0; d < 128; d++) { float v = kvS[tid * 132 + d]; ss += v * v; }
        float inv = 1.0f / fmaxf(sqrtf(ss), 1e-12f);
        for (int d = 0; d < 128; d++) kvS[tid * 132 + d] *= inv;
    }
    __syncthreads();

    {
        int it = tid >> 4, jt = tid & 15;
        int i0 = it * 4;
        float acc[4][8];
#pragma unroll
        for (int u = 0; u < 4; u++)
#pragma unroll
            for (int w = 0; w < 8; w++) acc[u][w] = 0.f;
        for (int d = 0; d < 128; d++) {
            float a[4], bb[8];
#pragma unroll
            for (int u = 0; u < 4; u++) a[u] = qS[(i0 + u) * 132 + d];
#pragma unroll
            for (int w = 0; w < 8; w++) bb[w] = kvS[(jt + w * 16) * 132 + d];
#pragma unroll
            for (int u = 0; u < 4; u++)
#pragma unroll
                for (int w = 0; w < 8; w++) acc[u][w] += a[u] * bb[w];
        }
#pragma unroll
        for (int u = 0; u < 4; u++) {
            int ti = tq[i0 + u];
#pragma unroll
            for (int w = 0; w < 8; w++) {
                int j = jt + w * 16;
                float v = (ti == tk[j]) ? SELF_VAL_ : acc[u][w] * SCALE_;
                dots[(i0 + u) * 128 + j] = v;
            }
        }
    }
    __syncthreads();

    {
        int warp = tid >> 5, lane = tid & 31;
        for (int rr = 0; rr < 8; rr++) {
            int i = warp * 8 + rr;
            float m = -3.0e38f;
#pragma unroll
            for (int u = 0; u < 4; u++) m = fmaxf(m, dots[i * 128 + lane + u * 32]);
            for (int o = 16; o > 0; o >>= 1) m = fmaxf(m, __shfl_xor_sync(0xffffffff, m, o));
            float s = 0.f;
#pragma unroll
            for (int u = 0; u < 4; u++) s += expf(dots[i * 128 + lane + u * 32] - m);
            for (int o = 16; o > 0; o >>= 1) s += __shfl_xor_sync(0xffffffff, s, o);
            float lse = m + logf(s);
#pragma unroll
            for (int u = 0; u < 4; u++) {
                int col = lane + u * 32;
                dots[i * 128 + col] = expf(dots[i * 128 + col] - lse);
            }
            if (lane == 0) lseS[i] = lse;
        }
    }
    __syncthreads();

    for (int idx = tid; idx < 128 * 128; idx += 256) {
        int j = idx >> 7, d = idx & 127;
        kvS[j * 132 + d] = vg[((size_t)(b * T_ + tk[j])) * DIM_ + h * DH_ + d];
    }
    __syncthreads();

    {
        int it = tid >> 4, jt = tid & 15;
        int i0 = it * 4;
        float acc[4][8];
#pragma unroll
        for (int u = 0; u < 4; u++)
#pragma unroll
            for (int w = 0; w < 8; w++) acc[u][w] = 0.f;
        for (int j = 0; j < 128; j++) {
            float p[4], vv[8];
#pragma unroll
            for (int u = 0; u < 4; u++) p[u] = dots[(i0 + u) * 128 + j];
#pragma unroll
            for (int w = 0; w < 8; w++) vv[w] = kvS[j * 132 + jt + w * 16];
#pragma unroll
            for (int u = 0; u < 4; u++)
#pragma unroll
                for (int w = 0; w < 8; w++) acc[u][w] += p[u] * vv[w];
        }
#pragma unroll
        for (int u = 0; u < 4; u++) {
            int i = i0 + u;
            size_t base = ((size_t)(bh * NHASH_ + hq[i]) * T_ + tq[i]) * DH_;
#pragma unroll
            for (int w = 0; w < 8; w++)
                orounds[base + jt + w * 16] = acc[u][w];
        }
    }
    if (tid < 64) {
        int i = tid;
        lseg[(bh * NHASH_ + hq[i]) * T_ + tq[i]] = lseS[i];
    }
}

// ================= combine hash rounds -> split bf16 =================
__global__ void combine_kernel(const float* __restrict__ orounds, const float* __restrict__ lse,
                               __nv_bfloat16* __restrict__ ah, __nv_bfloat16* __restrict__ al) {
    int blk = blockIdx.x;
    int bh = blk >> 12, t = blk & (T_ - 1);
    int b = bh >> 3, h = bh & 7;
    int d = threadIdx.x;
    float l[4];
#pragma unroll
    for (int hh = 0; hh < 4; hh++) l[hh] = lse[(bh * NHASH_ + hh) * T_ + t];
    float m = fmaxf(fmaxf(l[0], l[1]), fmaxf(l[2], l[3]));
    float s = 0.f;
#pragma unroll
    for (int hh = 0; hh < 4; hh++) s += expf(l[hh] - m);
    float ls = m + logf(s);
    float o = 0.f;
#pragma unroll
    for (int hh = 0; hh < 4; hh++)
        o += expf(l[hh] - ls) * orounds[((size_t)(bh * NHASH_ + hh) * T_ + t) * DH_ + d];
    size_t oi = ((size_t)(b * T_ + t)) * DIM_ + h * DH_ + d;
    __nv_bfloat16 hi = __float2bfloat16(o);
    ah[oi] = hi;
    al[oi] = __float2bfloat16(o - __bfloat162float(hi));
}

__global__ void add_kernel(const float* __restrict__ a, const float* __restrict__ b,
                           float* __restrict__ o, int n) {
    int i = blockIdx.x * blockDim.x + threadIdx.x;
    if (i < n) o[i] = a[i] + b[i];
}

// ================= host =================
extern "C" void kernel_launch(void* const* d_in, const int* in_sizes, int n_in,
                              void* d_out, int out_size) {
    const float* x     = (const float*)d_in[0];
    const float* ln1_g = (const float*)d_in[1];
    const float* ln1_b = (const float*)d_in[2];
    const float* Wqk   = (const float*)d_in[3];
    const float* Wv    = (const float*)d_in[4];
    const float* Wo    = (const float*)d_in[5];
    const float* bo    = (const float*)d_in[6];
    const float* ln2_g = (const float*)d_in[7];
    const float* ln2_b = (const float*)d_in[8];
    const float* W1    = (const float*)d_in[9];
    const float* b1    = (const float*)d_in[10];
    const float* W2    = (const float*)d_in[11];
    const float* b2    = (const float*)d_in[12];
    const float* rot   = (const float*)d_in[13];

    float *x1, *x2, *qk, *v, *orounds, *lse;
    int* keys;
    __nv_bfloat16 *xnh, *xnl, *ath, *atl, *ffh, *ffl;
    __nv_bfloat16 *wqkT, *wvT, *woT, *w1T, *w2T;
    cudaGetSymbolAddress((void**)&x1, g_x1);
    cudaGetSymbolAddress((void**)&x2, g_x2);
    cudaGetSymbolAddress((void**)&qk, g_qk);
    cudaGetSymbolAddress((void**)&v,  g_v);
    cudaGetSymbolAddress((void**)&orounds, g_orounds);
    cudaGetSymbolAddress((void**)&lse, g_lse);
    cudaGetSymbolAddress((void**)&keys, g_keys);
    cudaGetSymbolAddress((void**)&xnh, g_xnh);
    cudaGetSymbolAddress((void**)&xnl, g_xnl);
    cudaGetSymbolAddress((void**)&ath, g_ath);
    cudaGetSymbolAddress((void**)&atl, g_atl);
    cudaGetSymbolAddress((void**)&ffh, g_ffh);
    cudaGetSymbolAddress((void**)&ffl, g_ffl);
    cudaGetSymbolAddress((void**)&wqkT, g_wqkT);
    cudaGetSymbolAddress((void**)&wvT,  g_wvT);
    cudaGetSymbolAddress((void**)&woT,  g_woT);
    cudaGetSymbolAddress((void**)&w1T,  g_w1T);
    cudaGetSymbolAddress((void**)&w2T,  g_w2T);

    cudaFuncSetAttribute(hash_kernel, cudaFuncAttributeMaxDynamicSharedMemorySize, 98304);
    cudaFuncSetAttribute(attn_kernel, cudaFuncAttributeMaxDynamicSharedMemorySize, 135424);
    cudaFuncSetAttribute(gemm_mma,    cudaFuncAttributeMaxDynamicSharedMemorySize, GSMEM_);

    size_t bytes = (size_t)BT_ * DIM_ * sizeof(float);
    cudaMemcpyAsync(x1, x, bytes, cudaMemcpyDeviceToDevice, 0);
    cudaMemcpyAsync(x2, x, bytes, cudaMemcpyDeviceToDevice, 0);

    for (int dep = 0; dep < 2; dep++) {
        size_t o1 = (size_t)dep * 2 * DIM_ * DIM_;
        size_t o4 = (size_t)dep * 2 * FF_ * DIM_;
        tsplit_kernel<<<dim3(32, 32), dim3(32, 8)>>>(Wqk + (size_t)dep*DIM_*DIM_, DIM_, DIM_,
                                                     wqkT + o1, wqkT + o1 + DIM_*DIM_);
        tsplit_kernel<<<dim3(32, 32), dim3(32, 8)>>>(Wv  + (size_t)dep*DIM_*DIM_, DIM_, DIM_,
                                                     wvT + o1, wvT + o1 + DIM_*DIM_);
        tsplit_kernel<<<dim3(32, 32), dim3(32, 8)>>>(Wo  + (size_t)dep*DIM_*DIM_, DIM_, DIM_,
                                                     woT + o1, woT + o1 + DIM_*DIM_);
        tsplit_kernel<<<dim3(128, 32), dim3(32, 8)>>>(W1 + (size_t)dep*DIM_*FF_, DIM_, FF_,
                                                      w1T + o4, w1T + o4 + (size_t)FF_*DIM_);
        tsplit_kernel<<<dim3(32, 128), dim3(32, 8)>>>(W2 + (size_t)dep*FF_*DIM_, FF_, DIM_,
                                                      w2T + o4, w2T + o4 + (size_t)FF_*DIM_);
    }

    for (int dep = 0; dep < 2; dep++) {
        size_t o1 = (size_t)dep * 2 * DIM_ * DIM_;
        size_t o4 = (size_t)dep * 2 * FF_ * DIM_;
        const float* bov = bo + (size_t)dep * DIM_;
        const float* bb1 = b1 + (size_t)dep * FF_;
        const float* bb2 = b2 + (size_t)dep * DIM_;
        const float* rt  = rot + (size_t)dep * DH_ * NHASH_ * (NB_ / 2);

        ln_kernel<<<BT_, 256>>>(x2, ln1_g + dep * DIM_, ln1_b + dep * DIM_, xnh, xnl);
        // qk: 4-pass (hash-flip insurance), others 3-pass
        gemm_mma<<<dim3(8, 64), 256, GSMEM_>>>(xnh, xnl, wqkT + o1, wqkT + o1 + DIM_*DIM_,
                                               nullptr, nullptr, qk, nullptr, nullptr,
                                               BT_, DIM_, DIM_, 0, 4);
        gemm_mma<<<dim3(8, 64), 256, GSMEM_>>>(xnh, xnl, wvT + o1, wvT + o1 + DIM_*DIM_,
                                               nullptr, nullptr, v, nullptr, nullptr,
                                               BT_, DIM_, DIM_, 0, 3);
        hash_kernel<<<BH_ * 64, 256, 98304>>>(qk, rt, keys);
        sort_kernel<<<BH_ * NHASH_, 1024>>>(keys);
        attn_kernel<<<BH_ * NCH_, 256, 135424>>>(qk, v, keys, orounds, lse);
        combine_kernel<<<BH_ * T_, 128>>>(orounds, lse, ath, atl);
        gemm_mma<<<dim3(8, 64), 256, GSMEM_>>>(ath, atl, woT + o1, woT + o1 + DIM_*DIM_,
                                               bov, x1, x1, nullptr, nullptr,
                                               BT_, DIM_, DIM_, 0, 3);
        ln_kernel<<<BT_, 256>>>(x1, ln2_g + dep * DIM_, ln2_b + dep * DIM_, xnh, xnl);
        gemm_mma<<<dim3(32, 64), 256, GSMEM_>>>(xnh, xnl, w1T + o4, w1T + o4 + (size_t)FF_*DIM_,
                                                bb1, nullptr, nullptr, ffh, ffl,
                                                BT_, FF_, DIM_, 1, 3);
        gemm_mma<<<dim3(8, 64), 256, GSMEM_>>>(ffh, ffl, w2T + o4, w2T + o4 + (size_t)FF_*DIM_,
                                               bb2, x2, x2, nullptr, nullptr,
                                               BT_, DIM_, FF_, 0, 3);
    }
    add_kernel<<<(BT_ * DIM_ + 255) / 256, 256>>>(x1, x2, (float*)d_out, BT_ * DIM_);
}